// round 16
// baseline (speedup 1.0000x reference)
#include <cuda_runtime.h>
#include <cuda_fp16.h>
#include <cstdint>

// ---------------- problem constants ----------------
#define NWIN    4096
#define NTOK    49
#define HID     384
#define NHEAD   12
#define DHEAD   32
#define MTOT    (NWIN*NTOK)          // 200704
#define QSCALE  0.17677669529663687f // 32^-0.5

#define NBH     (NWIN*NHEAD)         // 49152
#define QK_STRIDE (49*40)
#define VT_STRIDE (32*72)

// ---------------- device scratch ----------------
__device__ __half g_qh[(size_t)NBH * QK_STRIDE];
__device__ __half g_ql[(size_t)NBH * QK_STRIDE];
__device__ __half g_kh[(size_t)NBH * QK_STRIDE];
__device__ __half g_kl[(size_t)NBH * QK_STRIDE];
__device__ __half g_vth[(size_t)NBH * VT_STRIDE];   // pads stay zero (.bss)
__device__ __half g_vtl[(size_t)NBH * VT_STRIDE];
__device__ float g_ao[(size_t)MTOT * HID];
__device__ float g_bias[NHEAD * NTOK * NTOK];

// ---------------- GEMM smem: A hi+lo, B hi only ----------------
struct SmemGemm {
    __half Ah[128 * 40];   // 10240 B
    __half Al[128 * 40];   // 10240 B
    __half Bh[96 * 40];    //  7680 B
};
union SmemU {
    SmemGemm g;
    float    c[128 * 96];  // 49152 B (C staging, qkv only)
};

// ---------------- helpers ----------------
__device__ __forceinline__ void mma_f16(float c[4], const uint32_t a[4], const uint32_t b[2]) {
    asm volatile(
        "mma.sync.aligned.m16n8k16.row.col.f32.f16.f16.f32 "
        "{%0,%1,%2,%3}, {%4,%5,%6,%7}, {%8,%9}, {%0,%1,%2,%3};\n"
        : "+f"(c[0]), "+f"(c[1]), "+f"(c[2]), "+f"(c[3])
        : "r"(a[0]), "r"(a[1]), "r"(a[2]), "r"(a[3]),
          "r"(b[0]), "r"(b[1]));
}

__device__ __forceinline__ void ldsm4(uint32_t r[4], uint32_t addr) {
    asm volatile("ldmatrix.sync.aligned.m8n8.x4.shared.b16 {%0,%1,%2,%3}, [%4];\n"
                 : "=r"(r[0]), "=r"(r[1]), "=r"(r[2]), "=r"(r[3]) : "r"(addr));
}

__device__ __forceinline__ uint32_t ld_h2(const __half* p) {
    return *reinterpret_cast<const uint32_t*>(p);
}

__device__ __forceinline__ void split_store(__half* hi, __half* lo, float a, float b) {
    __half2 h, l;
    h.x = __float2half_rn(a); l.x = __float2half_rn(a - __half2float(h.x));
    h.y = __float2half_rn(b); l.y = __float2half_rn(b - __half2float(h.y));
    *reinterpret_cast<__half2*>(hi) = h;
    *reinterpret_cast<__half2*>(lo) = l;
}

__device__ __forceinline__ void hi_store(__half* hi, float a, float b) {
    *reinterpret_cast<__half2*>(hi) = __floats2half2_rn(a, b);
}

__device__ __forceinline__ void cp16(uint32_t smem_addr, const void* gptr) {
    asm volatile("cp.async.cg.shared.global [%0], [%1], 16;\n"
                 :: "r"(smem_addr), "l"(gptr));
}

// ---------------- GEMM mainloop: C[128x96] = A*B^T, 4 warps, warp tile 32x96 ----------------
// 2-term split (A hi+lo, B hi). Register-prefetched next K-tile overlaps MMA burst.
__device__ __forceinline__ void run_gemm(const float* __restrict__ A,
                                         const float* __restrict__ B,
                                         int m0, int n0,
                                         SmemGemm* sm, float acc[2][12][4]) {
    const int tid  = threadIdx.x;   // 0..127
    const int lane = tid & 31;
    const int wid  = tid >> 5;      // 0..3 (M group)
    const int lr   = tid >> 3;      // 0..15
    const int lc   = (tid & 7) << 2;

    const float* Abase = A + (size_t)(m0 + lr) * 384 + lc;
    const float* Bbase = B + (size_t)(n0 + lr) * 384 + lc;

    const uint32_t AhB = (uint32_t)__cvta_generic_to_shared(sm->Ah);
    const uint32_t AlB = (uint32_t)__cvta_generic_to_shared(sm->Al);
    const uint32_t BhB = (uint32_t)__cvta_generic_to_shared(sm->Bh);

    const int aRow = wid * 32 + (lane & 15);
    const int aCol = (lane >> 4) << 3;
    const int bRow = (lane & 7) + ((lane & 16) >> 1);   // + ntp*16
    const int bCol = lane & 8;

    float4 ra[8], rb[6];
    #pragma unroll
    for (int p = 0; p < 8; p++)
        ra[p] = *reinterpret_cast<const float4*>(Abase + (size_t)p * 16 * 384);
    #pragma unroll
    for (int p = 0; p < 6; p++)
        rb[p] = *reinterpret_cast<const float4*>(Bbase + (size_t)p * 16 * 384);

    for (int k0 = 0; k0 < 384; k0 += 32) {
        __syncthreads();
        #pragma unroll
        for (int p = 0; p < 8; p++) {
            int row = lr + p * 16;
            split_store(&sm->Ah[row * 40 + lc],     &sm->Al[row * 40 + lc],     ra[p].x, ra[p].y);
            split_store(&sm->Ah[row * 40 + lc + 2], &sm->Al[row * 40 + lc + 2], ra[p].z, ra[p].w);
        }
        #pragma unroll
        for (int p = 0; p < 6; p++) {
            int row = lr + p * 16;
            hi_store(&sm->Bh[row * 40 + lc],     rb[p].x, rb[p].y);
            hi_store(&sm->Bh[row * 40 + lc + 2], rb[p].z, rb[p].w);
        }
        __syncthreads();

        if (k0 + 32 < 384) {
            #pragma unroll
            for (int p = 0; p < 8; p++)
                ra[p] = *reinterpret_cast<const float4*>(Abase + (size_t)p * 16 * 384 + k0 + 32);
            #pragma unroll
            for (int p = 0; p < 6; p++)
                rb[p] = *reinterpret_cast<const float4*>(Bbase + (size_t)p * 16 * 384 + k0 + 32);
        }

        #pragma unroll
        for (int ks = 0; ks < 32; ks += 16) {
            uint32_t ah[2][4], al[2][4], bh4[6][4];
            #pragma unroll
            for (int mt = 0; mt < 2; mt++) {
                const uint32_t aoff = (uint32_t)(((aRow + mt * 16) * 40 + ks + aCol) * 2);
                ldsm4(ah[mt], AhB + aoff);
                ldsm4(al[mt], AlB + aoff);
            }
            #pragma unroll
            for (int ntp = 0; ntp < 6; ntp++) {
                const uint32_t boff = (uint32_t)(((bRow + ntp * 16) * 40 + ks + bCol) * 2);
                ldsm4(bh4[ntp], BhB + boff);
            }
            #pragma unroll
            for (int mt = 0; mt < 2; mt++)
                #pragma unroll
                for (int nt = 0; nt < 12; nt++) {
                    const uint32_t* bh = &bh4[nt >> 1][(nt & 1) * 2];
                    mma_f16(acc[mt][nt], ah[mt], bh);
                    mma_f16(acc[mt][nt], al[mt], bh);
                }
        }
    }
}

// ---------------- K0: dense relative position bias ----------------
__global__ void bias_kernel(const float* __restrict__ table, const int* __restrict__ ridx) {
    int e = blockIdx.x * 256 + threadIdx.x;
    if (e < NHEAD * NTOK * NTOK) {
        int h = e / (NTOK * NTOK);
        int r = e - h * (NTOK * NTOK);
        g_bias[e] = table[ridx[r] * NHEAD + h];
    }
}

// ---------------- K1: QKV projection + split scatter ----------------
__global__ void __launch_bounds__(128) qkv_kernel(const float* __restrict__ x,
                                                  const float* __restrict__ qkv_w,
                                                  const float* __restrict__ qkv_b) {
    __shared__ SmemU sm;
    float acc[2][12][4];
    #pragma unroll
    for (int a = 0; a < 2; a++)
        #pragma unroll
        for (int b = 0; b < 12; b++)
            #pragma unroll
            for (int c = 0; c < 4; c++) acc[a][b][c] = 0.f;

    const int n0 = blockIdx.x * 96;
    const int m0 = blockIdx.y * 128;
    run_gemm(x, qkv_w, m0, n0, &sm.g, acc);
    __syncthreads();

    const int lane = threadIdx.x & 31, wid = threadIdx.x >> 5;
    const int rr = lane >> 2, c2 = (lane & 3) << 1;
    #pragma unroll
    for (int mt = 0; mt < 2; mt++)
        #pragma unroll
        for (int nt = 0; nt < 12; nt++) {
            int row = wid * 32 + mt * 16 + rr;
            int col = nt * 8 + c2;
            sm.c[row * 96 + col]           = acc[mt][nt][0];
            sm.c[row * 96 + col + 1]       = acc[mt][nt][1];
            sm.c[(row + 8) * 96 + col]     = acc[mt][nt][2];
            sm.c[(row + 8) * 96 + col + 1] = acc[mt][nt][3];
        }
    __syncthreads();

    const int h = blockIdx.x;
    // q,k: split hi/lo, planar layout [w,h][t*40+dd]
    for (int e = threadIdx.x; e < 128 * 64; e += 128) {
        int dd  = e & 31;
        int sp  = (e >> 5) & 1;
        int row = e >> 6;
        int col = dd * 3 + sp;
        float val = sm.c[row * 96 + col] + qkv_b[n0 + col];
        if (sp == 0) val *= QSCALE;
        __half hi = __float2half_rn(val);
        __half lo = __float2half_rn(val - __half2float(hi));
        int m = m0 + row;
        int ww = m / 49;
        int t  = m - ww * 49;
        size_t o = (size_t)(ww * NHEAD + h) * QK_STRIDE + t * 40 + dd;
        if (sp == 0) { g_qh[o] = hi; g_ql[o] = lo; }
        else         { g_kh[o] = hi; g_kl[o] = lo; }
    }
    // v: transposed layout [w,h][dd*72+t]
    for (int e = threadIdx.x; e < 128 * 32; e += 128) {
        int row = e & 127;
        int dd  = e >> 7;
        int col = dd * 3 + 2;
        float val = sm.c[row * 96 + col] + qkv_b[n0 + col];
        __half hi = __float2half_rn(val);
        __half lo = __float2half_rn(val - __half2float(hi));
        int m = m0 + row;
        int ww = m / 49;
        int t  = m - ww * 49;
        size_t o = (size_t)(ww * NHEAD + h) * VT_STRIDE + dd * 72 + t;
        g_vth[o] = hi;
        g_vtl[o] = lo;
    }
}

// ---------------- K2: attention (3-term split MMA, __expf softmax) ----------------
struct AttnSmem {
    union {
        struct {
            __half Qh[64 * 40];
            __half Ql[64 * 40];
            __half Kh[64 * 40];
            __half Kl[64 * 40];
        } qk;
        struct {
            __half Ph[64 * 72];
            __half Pl[64 * 72];
        } p;
    } u;
    __half Vth[32 * 72];
    __half Vtl[32 * 72];
    float  sc[64 * 57];
};

__global__ void __launch_bounds__(128) attn_kernel() {
    const int bid = blockIdx.x;        // ww*NHEAD + h
    const int h   = bid % NHEAD;
    const int ww  = bid / NHEAD;

    __shared__ AttnSmem s;

    const int tid = threadIdx.x, lane = tid & 31, wm = tid >> 5;
    const int rr  = lane >> 2;
    const int qoff = (lane & 3) << 1;

    {
        const uint32_t smQ = (uint32_t)__cvta_generic_to_shared(s.u.qk.Qh);
        const uint32_t smV = (uint32_t)__cvta_generic_to_shared(s.Vth);
        const char* gqh = (const char*)g_qh + (size_t)bid * (QK_STRIDE * 2);
        const char* gql = (const char*)g_ql + (size_t)bid * (QK_STRIDE * 2);
        const char* gkh = (const char*)g_kh + (size_t)bid * (QK_STRIDE * 2);
        const char* gkl = (const char*)g_kl + (size_t)bid * (QK_STRIDE * 2);
        const char* gvh = (const char*)g_vth + (size_t)bid * (VT_STRIDE * 2);
        const char* gvl = (const char*)g_vtl + (size_t)bid * (VT_STRIDE * 2);
        for (int e = tid; e < 245; e += 128) {
            cp16(smQ + e * 16,         gqh + e * 16);
            cp16(smQ + 5120 + e * 16,  gql + e * 16);
            cp16(smQ + 10240 + e * 16, gkh + e * 16);
            cp16(smQ + 15360 + e * 16, gkl + e * 16);
        }
        for (int e = tid; e < 288; e += 128) {
            cp16(smV + e * 16,        gvh + e * 16);
            cp16(smV + 4608 + e * 16, gvl + e * 16);
        }
        asm volatile("cp.async.commit_group;\n");
        asm volatile("cp.async.wait_group 0;\n" ::: "memory");
    }
    __syncthreads();

    // ---- scores ----
    {
        float acc[7][4];
        #pragma unroll
        for (int nt = 0; nt < 7; nt++)
            #pragma unroll
            for (int c = 0; c < 4; c++) acc[nt][c] = 0.f;

        #pragma unroll
        for (int kt = 0; kt < 32; kt += 16) {
            uint32_t ah[4], al[4];
            const int rb = wm * 16 + rr;
            const int cc = kt + qoff;
            ah[0] = ld_h2(&s.u.qk.Qh[rb * 40 + cc]);
            ah[1] = ld_h2(&s.u.qk.Qh[(rb + 8) * 40 + cc]);
            ah[2] = ld_h2(&s.u.qk.Qh[rb * 40 + cc + 8]);
            ah[3] = ld_h2(&s.u.qk.Qh[(rb + 8) * 40 + cc + 8]);
            al[0] = ld_h2(&s.u.qk.Ql[rb * 40 + cc]);
            al[1] = ld_h2(&s.u.qk.Ql[(rb + 8) * 40 + cc]);
            al[2] = ld_h2(&s.u.qk.Ql[rb * 40 + cc + 8]);
            al[3] = ld_h2(&s.u.qk.Ql[(rb + 8) * 40 + cc + 8]);
            #pragma unroll
            for (int nt = 0; nt < 7; nt++) {
                const int nb = nt * 8 + rr;
                uint32_t bh[2], bl[2];
                bh[0] = ld_h2(&s.u.qk.Kh[nb * 40 + cc]);
                bh[1] = ld_h2(&s.u.qk.Kh[nb * 40 + cc + 8]);
                bl[0] = ld_h2(&s.u.qk.Kl[nb * 40 + cc]);
                bl[1] = ld_h2(&s.u.qk.Kl[nb * 40 + cc + 8]);
                mma_f16(acc[nt], ah, bh);
                mma_f16(acc[nt], ah, bl);
                mma_f16(acc[nt], al, bh);
            }
        }
        const int r0 = wm * 16 + rr;
        #pragma unroll
        for (int nt = 0; nt < 7; nt++) {
            const int c = nt * 8 + qoff;
            s.sc[r0 * 57 + c]           = acc[nt][0];
            s.sc[r0 * 57 + c + 1]       = acc[nt][1];
            s.sc[(r0 + 8) * 57 + c]     = acc[nt][2];
            s.sc[(r0 + 8) * 57 + c + 1] = acc[nt][3];
        }
    }
    __syncthreads();

    // ---- softmax (+bias), write P split fp16 ----
    const float* bias = &g_bias[h * (NTOK * NTOK)];
    for (int i = wm; i < NTOK; i += 4) {
        const int j2 = 32 + lane;
        const bool v2 = (j2 < NTOK);
        float s0 = s.sc[i * 57 + lane] + bias[i * 49 + lane];
        float s1 = v2 ? (s.sc[i * 57 + j2] + bias[i * 49 + j2]) : -3.0e38f;
        float mx = fmaxf(s0, s1);
        #pragma unroll
        for (int o = 16; o; o >>= 1) mx = fmaxf(mx, __shfl_xor_sync(0xffffffffu, mx, o));
        float p0 = __expf(s0 - mx);
        float p1 = v2 ? __expf(s1 - mx) : 0.f;
        float sum = p0 + p1;
        #pragma unroll
        for (int o = 16; o; o >>= 1) sum += __shfl_xor_sync(0xffffffffu, sum, o);
        float inv = 1.f / sum;
        p0 *= inv;
        p1 = v2 ? p1 * inv : 0.f;
        {
            __half hi = __float2half_rn(p0);
            __half lo = __float2half_rn(p0 - __half2float(hi));
            s.u.p.Ph[i * 72 + lane] = hi;
            s.u.p.Pl[i * 72 + lane] = lo;
            __half hi1 = __float2half_rn(p1);
            __half lo1 = __float2half_rn(p1 - __half2float(hi1));
            s.u.p.Ph[i * 72 + j2] = hi1;
            s.u.p.Pl[i * 72 + j2] = lo1;
        }
    }
    __syncthreads();

    // ---- PV ----
    {
        float acc[4][4];
        #pragma unroll
        for (int nt = 0; nt < 4; nt++)
            #pragma unroll
            for (int c = 0; c < 4; c++) acc[nt][c] = 0.f;

        #pragma unroll
        for (int kt = 0; kt < 64; kt += 16) {
            uint32_t ah[4], al[4];
            const int rb = wm * 16 + rr;
            const int cc = kt + qoff;
            ah[0] = ld_h2(&s.u.p.Ph[rb * 72 + cc]);
            ah[1] = ld_h2(&s.u.p.Ph[(rb + 8) * 72 + cc]);
            ah[2] = ld_h2(&s.u.p.Ph[rb * 72 + cc + 8]);
            ah[3] = ld_h2(&s.u.p.Ph[(rb + 8) * 72 + cc + 8]);
            al[0] = ld_h2(&s.u.p.Pl[rb * 72 + cc]);
            al[1] = ld_h2(&s.u.p.Pl[(rb + 8) * 72 + cc]);
            al[2] = ld_h2(&s.u.p.Pl[rb * 72 + cc + 8]);
            al[3] = ld_h2(&s.u.p.Pl[(rb + 8) * 72 + cc + 8]);
            #pragma unroll
            for (int nt = 0; nt < 4; nt++) {
                const int nb = nt * 8 + rr;
                uint32_t bh[2], bl[2];
                bh[0] = ld_h2(&s.Vth[nb * 72 + cc]);
                bh[1] = ld_h2(&s.Vth[nb * 72 + cc + 8]);
                bl[0] = ld_h2(&s.Vtl[nb * 72 + cc]);
                bl[1] = ld_h2(&s.Vtl[nb * 72 + cc + 8]);
                mma_f16(acc[nt], ah, bh);
                mma_f16(acc[nt], ah, bl);
                mma_f16(acc[nt], al, bh);
            }
        }
        const int r0 = wm * 16 + rr;
        #pragma unroll
        for (int nt = 0; nt < 4; nt++) {
            const int d = nt * 8 + qoff;
            if (r0 < NTOK) {
                float2 v = make_float2(acc[nt][0], acc[nt][1]);
                *reinterpret_cast<float2*>(&g_ao[((size_t)ww * NTOK + r0) * HID + h * DHEAD + d]) = v;
            }
            if (r0 + 8 < NTOK) {
                float2 v = make_float2(acc[nt][2], acc[nt][3]);
                *reinterpret_cast<float2*>(&g_ao[((size_t)ww * NTOK + r0 + 8) * HID + h * DHEAD + d]) = v;
            }
        }
    }
}

// ---------------- K3: output projection ----------------
__global__ void __launch_bounds__(128) fc_kernel(const float* __restrict__ fc_w,
                                                 const float* __restrict__ fc_b,
                                                 float* __restrict__ out) {
    __shared__ SmemGemm sm;
    float acc[2][12][4];
    #pragma unroll
    for (int a = 0; a < 2; a++)
        #pragma unroll
        for (int b = 0; b < 12; b++)
            #pragma unroll
            for (int c = 0; c < 4; c++) acc[a][b][c] = 0.f;

    const int n0 = blockIdx.x * 96;
    const int m0 = blockIdx.y * 128;
    run_gemm(g_ao, fc_w, m0, n0, &sm, acc);

    const int lane = threadIdx.x & 31, wid = threadIdx.x >> 5;
    const int rr = lane >> 2, c2 = (lane & 3) << 1;
    #pragma unroll
    for (int mt = 0; mt < 2; mt++)
        #pragma unroll
        for (int nt = 0; nt < 12; nt++) {
            int row = m0 + wid * 32 + mt * 16 + rr;
            int col = n0 + nt * 8 + c2;
            float b0 = fc_b[col], b1 = fc_b[col + 1];
            float2 v0 = make_float2(acc[mt][nt][0] + b0, acc[mt][nt][1] + b1);
            float2 v1 = make_float2(acc[mt][nt][2] + b0, acc[mt][nt][3] + b1);
            *reinterpret_cast<float2*>(&out[(size_t)row * 384 + col])       = v0;
            *reinterpret_cast<float2*>(&out[(size_t)(row + 8) * 384 + col]) = v1;
        }
}

// ---------------- launch ----------------
extern "C" void kernel_launch(void* const* d_in, const int* in_sizes, int n_in,
                              void* d_out, int out_size) {
    const float* x    = (const float*)d_in[0];
    const float* tbl  = (const float*)d_in[1];
    const float* qw   = (const float*)d_in[2];
    const float* qb   = (const float*)d_in[3];
    const float* fw   = (const float*)d_in[4];
    const float* fb   = (const float*)d_in[5];
    const int*   ridx = (const int*)d_in[6];
    float* out = (float*)d_out;

    bias_kernel<<<(NHEAD * NTOK * NTOK + 255) / 256, 256>>>(tbl, ridx);
    qkv_kernel<<<dim3(NHEAD, MTOT / 128), 128>>>(x, qw, qb);
    attn_kernel<<<NWIN * NHEAD, 128>>>();
    fc_kernel<<<dim3(HID / 96, MTOT / 128), 128>>>(fw, fb, out);
}

// round 17
// speedup vs baseline: 1.1172x; 1.1172x over previous
#include <cuda_runtime.h>
#include <cuda_fp16.h>
#include <cstdint>

// ---------------- problem constants ----------------
#define NWIN    4096
#define NTOK    49
#define HID     384
#define NHEAD   12
#define DHEAD   32
#define MTOT    (NWIN*NTOK)          // 200704
#define QSCALE  0.17677669529663687f // 32^-0.5

#define NBH     (NWIN*NHEAD)         // 49152
#define QK_STRIDE (49*40)
#define VT_STRIDE (32*72)

// ---------------- device scratch ----------------
__device__ __half g_qh[(size_t)NBH * QK_STRIDE];
__device__ __half g_ql[(size_t)NBH * QK_STRIDE];
__device__ __half g_kh[(size_t)NBH * QK_STRIDE];
__device__ __half g_vth[(size_t)NBH * VT_STRIDE];   // pads stay zero (.bss)
__device__ float g_ao[(size_t)MTOT * HID];
__device__ float g_bias[NHEAD * NTOK * NTOK];

// ---------------- GEMM smem: A hi+lo, B hi only ----------------
struct SmemGemm {
    __half Ah[128 * 40];   // 10240 B
    __half Al[128 * 40];   // 10240 B
    __half Bh[96 * 40];    //  7680 B
};
union SmemU {
    SmemGemm g;
    float    c[128 * 96];  // 49152 B (C staging, qkv only)
};

// ---------------- helpers ----------------
__device__ __forceinline__ void mma_f16(float c[4], const uint32_t a[4], const uint32_t b[2]) {
    asm volatile(
        "mma.sync.aligned.m16n8k16.row.col.f32.f16.f16.f32 "
        "{%0,%1,%2,%3}, {%4,%5,%6,%7}, {%8,%9}, {%0,%1,%2,%3};\n"
        : "+f"(c[0]), "+f"(c[1]), "+f"(c[2]), "+f"(c[3])
        : "r"(a[0]), "r"(a[1]), "r"(a[2]), "r"(a[3]),
          "r"(b[0]), "r"(b[1]));
}

__device__ __forceinline__ void ldsm4(uint32_t r[4], uint32_t addr) {
    asm volatile("ldmatrix.sync.aligned.m8n8.x4.shared.b16 {%0,%1,%2,%3}, [%4];\n"
                 : "=r"(r[0]), "=r"(r[1]), "=r"(r[2]), "=r"(r[3]) : "r"(addr));
}

__device__ __forceinline__ uint32_t ld_h2(const __half* p) {
    return *reinterpret_cast<const uint32_t*>(p);
}

__device__ __forceinline__ void split_store(__half* hi, __half* lo, float a, float b) {
    __half2 h, l;
    h.x = __float2half_rn(a); l.x = __float2half_rn(a - __half2float(h.x));
    h.y = __float2half_rn(b); l.y = __float2half_rn(b - __half2float(h.y));
    *reinterpret_cast<__half2*>(hi) = h;
    *reinterpret_cast<__half2*>(lo) = l;
}

__device__ __forceinline__ void hi_store(__half* hi, float a, float b) {
    *reinterpret_cast<__half2*>(hi) = __floats2half2_rn(a, b);
}

__device__ __forceinline__ void cp16(uint32_t smem_addr, const void* gptr) {
    asm volatile("cp.async.cg.shared.global [%0], [%1], 16;\n"
                 :: "r"(smem_addr), "l"(gptr));
}

// ---------------- GEMM mainloop: C[128x96] = A*B^T, 4 warps, warp tile 32x96 ----------------
// 2-term split (A hi+lo, B hi). PRE: register-prefetch next K-tile (fc only —
// costs regs/occupancy; wins when epilogue is light).
template<bool PRE>
__device__ __forceinline__ void run_gemm(const float* __restrict__ A,
                                         const float* __restrict__ B,
                                         int m0, int n0,
                                         SmemGemm* sm, float acc[2][12][4]) {
    const int tid  = threadIdx.x;   // 0..127
    const int lane = tid & 31;
    const int wid  = tid >> 5;      // 0..3 (M group)
    const int lr   = tid >> 3;      // 0..15
    const int lc   = (tid & 7) << 2;

    const float* Abase = A + (size_t)(m0 + lr) * 384 + lc;
    const float* Bbase = B + (size_t)(n0 + lr) * 384 + lc;

    const uint32_t AhB = (uint32_t)__cvta_generic_to_shared(sm->Ah);
    const uint32_t AlB = (uint32_t)__cvta_generic_to_shared(sm->Al);
    const uint32_t BhB = (uint32_t)__cvta_generic_to_shared(sm->Bh);

    const int aRow = wid * 32 + (lane & 15);
    const int aCol = (lane >> 4) << 3;
    const int bRow = (lane & 7) + ((lane & 16) >> 1);   // + ntp*16
    const int bCol = lane & 8;

    float4 ra[8], rb[6];
    if (PRE) {
        #pragma unroll
        for (int p = 0; p < 8; p++)
            ra[p] = *reinterpret_cast<const float4*>(Abase + (size_t)p * 16 * 384);
        #pragma unroll
        for (int p = 0; p < 6; p++)
            rb[p] = *reinterpret_cast<const float4*>(Bbase + (size_t)p * 16 * 384);
    }

    for (int k0 = 0; k0 < 384; k0 += 32) {
        __syncthreads();
        if (PRE) {
            #pragma unroll
            for (int p = 0; p < 8; p++) {
                int row = lr + p * 16;
                split_store(&sm->Ah[row * 40 + lc],     &sm->Al[row * 40 + lc],     ra[p].x, ra[p].y);
                split_store(&sm->Ah[row * 40 + lc + 2], &sm->Al[row * 40 + lc + 2], ra[p].z, ra[p].w);
            }
            #pragma unroll
            for (int p = 0; p < 6; p++) {
                int row = lr + p * 16;
                hi_store(&sm->Bh[row * 40 + lc],     rb[p].x, rb[p].y);
                hi_store(&sm->Bh[row * 40 + lc + 2], rb[p].z, rb[p].w);
            }
        } else {
            #pragma unroll
            for (int p = 0; p < 8; p++) {
                int row = lr + p * 16;
                float4 v = *reinterpret_cast<const float4*>(Abase + (size_t)p * 16 * 384 + k0);
                split_store(&sm->Ah[row * 40 + lc],     &sm->Al[row * 40 + lc],     v.x, v.y);
                split_store(&sm->Ah[row * 40 + lc + 2], &sm->Al[row * 40 + lc + 2], v.z, v.w);
            }
            #pragma unroll
            for (int p = 0; p < 6; p++) {
                int row = lr + p * 16;
                float4 v = *reinterpret_cast<const float4*>(Bbase + (size_t)p * 16 * 384 + k0);
                hi_store(&sm->Bh[row * 40 + lc],     v.x, v.y);
                hi_store(&sm->Bh[row * 40 + lc + 2], v.z, v.w);
            }
        }
        __syncthreads();

        if (PRE && k0 + 32 < 384) {
            #pragma unroll
            for (int p = 0; p < 8; p++)
                ra[p] = *reinterpret_cast<const float4*>(Abase + (size_t)p * 16 * 384 + k0 + 32);
            #pragma unroll
            for (int p = 0; p < 6; p++)
                rb[p] = *reinterpret_cast<const float4*>(Bbase + (size_t)p * 16 * 384 + k0 + 32);
        }

        #pragma unroll
        for (int ks = 0; ks < 32; ks += 16) {
            uint32_t ah[2][4], al[2][4], bh4[6][4];
            #pragma unroll
            for (int mt = 0; mt < 2; mt++) {
                const uint32_t aoff = (uint32_t)(((aRow + mt * 16) * 40 + ks + aCol) * 2);
                ldsm4(ah[mt], AhB + aoff);
                ldsm4(al[mt], AlB + aoff);
            }
            #pragma unroll
            for (int ntp = 0; ntp < 6; ntp++) {
                const uint32_t boff = (uint32_t)(((bRow + ntp * 16) * 40 + ks + bCol) * 2);
                ldsm4(bh4[ntp], BhB + boff);
            }
            #pragma unroll
            for (int mt = 0; mt < 2; mt++)
                #pragma unroll
                for (int nt = 0; nt < 12; nt++) {
                    const uint32_t* bh = &bh4[nt >> 1][(nt & 1) * 2];
                    mma_f16(acc[mt][nt], ah[mt], bh);
                    mma_f16(acc[mt][nt], al[mt], bh);
                }
        }
    }
}

// ---------------- K0: dense relative position bias ----------------
__global__ void bias_kernel(const float* __restrict__ table, const int* __restrict__ ridx) {
    int e = blockIdx.x * 256 + threadIdx.x;
    if (e < NHEAD * NTOK * NTOK) {
        int h = e / (NTOK * NTOK);
        int r = e - h * (NTOK * NTOK);
        g_bias[e] = table[ridx[r] * NHEAD + h];
    }
}

// ---------------- K1: QKV projection + split scatter ----------------
__global__ void __launch_bounds__(128) qkv_kernel(const float* __restrict__ x,
                                                  const float* __restrict__ qkv_w,
                                                  const float* __restrict__ qkv_b) {
    __shared__ SmemU sm;
    float acc[2][12][4];
    #pragma unroll
    for (int a = 0; a < 2; a++)
        #pragma unroll
        for (int b = 0; b < 12; b++)
            #pragma unroll
            for (int c = 0; c < 4; c++) acc[a][b][c] = 0.f;

    const int n0 = blockIdx.x * 96;
    const int m0 = blockIdx.y * 128;
    run_gemm<false>(x, qkv_w, m0, n0, &sm.g, acc);
    __syncthreads();

    const int lane = threadIdx.x & 31, wid = threadIdx.x >> 5;
    const int rr = lane >> 2, c2 = (lane & 3) << 1;
    #pragma unroll
    for (int mt = 0; mt < 2; mt++)
        #pragma unroll
        for (int nt = 0; nt < 12; nt++) {
            int row = wid * 32 + mt * 16 + rr;
            int col = nt * 8 + c2;
            sm.c[row * 96 + col]           = acc[mt][nt][0];
            sm.c[row * 96 + col + 1]       = acc[mt][nt][1];
            sm.c[(row + 8) * 96 + col]     = acc[mt][nt][2];
            sm.c[(row + 8) * 96 + col + 1] = acc[mt][nt][3];
        }
    __syncthreads();

    const int h = blockIdx.x;
    // q: split hi/lo; k: hi only. Planar layout [w,h][t*40+dd].
    for (int e = threadIdx.x; e < 128 * 64; e += 128) {
        int dd  = e & 31;
        int sp  = (e >> 5) & 1;
        int row = e >> 6;
        int col = dd * 3 + sp;
        float val = sm.c[row * 96 + col] + qkv_b[n0 + col];
        int m = m0 + row;
        int ww = m / 49;
        int t  = m - ww * 49;
        size_t o = (size_t)(ww * NHEAD + h) * QK_STRIDE + t * 40 + dd;
        if (sp == 0) {
            val *= QSCALE;
            __half hi = __float2half_rn(val);
            __half lo = __float2half_rn(val - __half2float(hi));
            g_qh[o] = hi; g_ql[o] = lo;
        } else {
            g_kh[o] = __float2half_rn(val);
        }
    }
    // v: hi only, transposed layout [w,h][dd*72+t]
    for (int e = threadIdx.x; e < 128 * 32; e += 128) {
        int row = e & 127;
        int dd  = e >> 7;
        int col = dd * 3 + 2;
        float val = sm.c[row * 96 + col] + qkv_b[n0 + col];
        int m = m0 + row;
        int ww = m / 49;
        int t  = m - ww * 49;
        g_vth[(size_t)(ww * NHEAD + h) * VT_STRIDE + dd * 72 + t] = __float2half_rn(val);
    }
}

// ---------------- K2: attention (A-side 2-term split MMA, __expf softmax) ----------------
struct AttnSmem {
    union {
        struct {
            __half Qh[64 * 40];   //     0 ..  5120
            __half Ql[64 * 40];   //  5120 .. 10240
            __half Kh[64 * 40];   // 10240 .. 15360
        } qk;
        struct {
            __half Ph[64 * 72];
            __half Pl[64 * 72];
        } p;                       // 18432 B
    } u;
    __half Vth[32 * 72];           // 4608 B
    float  sc[64 * 57];            // 14592 B
};                                  // ~37.6 KB

__global__ void __launch_bounds__(128) attn_kernel() {
    const int bid = blockIdx.x;        // ww*NHEAD + h
    const int h   = bid % NHEAD;
    const int ww  = bid / NHEAD;

    __shared__ AttnSmem s;

    const int tid = threadIdx.x, lane = tid & 31, wm = tid >> 5;
    const int rr  = lane >> 2;
    const int qoff = (lane & 3) << 1;

    {
        const uint32_t smQ = (uint32_t)__cvta_generic_to_shared(s.u.qk.Qh);
        const uint32_t smV = (uint32_t)__cvta_generic_to_shared(s.Vth);
        const char* gqh = (const char*)g_qh + (size_t)bid * (QK_STRIDE * 2);
        const char* gql = (const char*)g_ql + (size_t)bid * (QK_STRIDE * 2);
        const char* gkh = (const char*)g_kh + (size_t)bid * (QK_STRIDE * 2);
        const char* gvh = (const char*)g_vth + (size_t)bid * (VT_STRIDE * 2);
        for (int e = tid; e < 245; e += 128) {
            cp16(smQ + e * 16,         gqh + e * 16);
            cp16(smQ + 5120 + e * 16,  gql + e * 16);
            cp16(smQ + 10240 + e * 16, gkh + e * 16);
        }
        for (int e = tid; e < 288; e += 128)
            cp16(smV + e * 16, gvh + e * 16);
        asm volatile("cp.async.commit_group;\n");
        asm volatile("cp.async.wait_group 0;\n" ::: "memory");
    }
    __syncthreads();

    // ---- scores: S = Q(hi+lo) @ K_hi^T ----
    {
        float acc[7][4];
        #pragma unroll
        for (int nt = 0; nt < 7; nt++)
            #pragma unroll
            for (int c = 0; c < 4; c++) acc[nt][c] = 0.f;

        #pragma unroll
        for (int kt = 0; kt < 32; kt += 16) {
            uint32_t ah[4], al[4];
            const int rb = wm * 16 + rr;
            const int cc = kt + qoff;
            ah[0] = ld_h2(&s.u.qk.Qh[rb * 40 + cc]);
            ah[1] = ld_h2(&s.u.qk.Qh[(rb + 8) * 40 + cc]);
            ah[2] = ld_h2(&s.u.qk.Qh[rb * 40 + cc + 8]);
            ah[3] = ld_h2(&s.u.qk.Qh[(rb + 8) * 40 + cc + 8]);
            al[0] = ld_h2(&s.u.qk.Ql[rb * 40 + cc]);
            al[1] = ld_h2(&s.u.qk.Ql[(rb + 8) * 40 + cc]);
            al[2] = ld_h2(&s.u.qk.Ql[rb * 40 + cc + 8]);
            al[3] = ld_h2(&s.u.qk.Ql[(rb + 8) * 40 + cc + 8]);
            #pragma unroll
            for (int nt = 0; nt < 7; nt++) {
                const int nb = nt * 8 + rr;
                uint32_t bh[2];
                bh[0] = ld_h2(&s.u.qk.Kh[nb * 40 + cc]);
                bh[1] = ld_h2(&s.u.qk.Kh[nb * 40 + cc + 8]);
                mma_f16(acc[nt], ah, bh);
                mma_f16(acc[nt], al, bh);
            }
        }
        const int r0 = wm * 16 + rr;
        #pragma unroll
        for (int nt = 0; nt < 7; nt++) {
            const int c = nt * 8 + qoff;
            s.sc[r0 * 57 + c]           = acc[nt][0];
            s.sc[r0 * 57 + c + 1]       = acc[nt][1];
            s.sc[(r0 + 8) * 57 + c]     = acc[nt][2];
            s.sc[(r0 + 8) * 57 + c + 1] = acc[nt][3];
        }
    }
    __syncthreads();

    // ---- softmax (+bias), write P split fp16 ----
    const float* bias = &g_bias[h * (NTOK * NTOK)];
    for (int i = wm; i < NTOK; i += 4) {
        const int j2 = 32 + lane;
        const bool v2 = (j2 < NTOK);
        float s0 = s.sc[i * 57 + lane] + bias[i * 49 + lane];
        float s1 = v2 ? (s.sc[i * 57 + j2] + bias[i * 49 + j2]) : -3.0e38f;
        float mx = fmaxf(s0, s1);
        #pragma unroll
        for (int o = 16; o; o >>= 1) mx = fmaxf(mx, __shfl_xor_sync(0xffffffffu, mx, o));
        float p0 = __expf(s0 - mx);
        float p1 = v2 ? __expf(s1 - mx) : 0.f;
        float sum = p0 + p1;
        #pragma unroll
        for (int o = 16; o; o >>= 1) sum += __shfl_xor_sync(0xffffffffu, sum, o);
        float inv = 1.f / sum;
        p0 *= inv;
        p1 = v2 ? p1 * inv : 0.f;
        {
            __half hi = __float2half_rn(p0);
            __half lo = __float2half_rn(p0 - __half2float(hi));
            s.u.p.Ph[i * 72 + lane] = hi;
            s.u.p.Pl[i * 72 + lane] = lo;
            __half hi1 = __float2half_rn(p1);
            __half lo1 = __float2half_rn(p1 - __half2float(hi1));
            s.u.p.Ph[i * 72 + j2] = hi1;
            s.u.p.Pl[i * 72 + j2] = lo1;
        }
    }
    __syncthreads();

    // ---- PV: O = P(hi+lo) @ V_hi ----
    {
        float acc[4][4];
        #pragma unroll
        for (int nt = 0; nt < 4; nt++)
            #pragma unroll
            for (int c = 0; c < 4; c++) acc[nt][c] = 0.f;

        #pragma unroll
        for (int kt = 0; kt < 64; kt += 16) {
            uint32_t ah[4], al[4];
            const int rb = wm * 16 + rr;
            const int cc = kt + qoff;
            ah[0] = ld_h2(&s.u.p.Ph[rb * 72 + cc]);
            ah[1] = ld_h2(&s.u.p.Ph[(rb + 8) * 72 + cc]);
            ah[2] = ld_h2(&s.u.p.Ph[rb * 72 + cc + 8]);
            ah[3] = ld_h2(&s.u.p.Ph[(rb + 8) * 72 + cc + 8]);
            al[0] = ld_h2(&s.u.p.Pl[rb * 72 + cc]);
            al[1] = ld_h2(&s.u.p.Pl[(rb + 8) * 72 + cc]);
            al[2] = ld_h2(&s.u.p.Pl[rb * 72 + cc + 8]);
            al[3] = ld_h2(&s.u.p.Pl[(rb + 8) * 72 + cc + 8]);
            #pragma unroll
            for (int nt = 0; nt < 4; nt++) {
                const int nb = nt * 8 + rr;
                uint32_t bh[2];
                bh[0] = ld_h2(&s.Vth[nb * 72 + cc]);
                bh[1] = ld_h2(&s.Vth[nb * 72 + cc + 8]);
                mma_f16(acc[nt], ah, bh);
                mma_f16(acc[nt], al, bh);
            }
        }
        const int r0 = wm * 16 + rr;
        #pragma unroll
        for (int nt = 0; nt < 4; nt++) {
            const int d = nt * 8 + qoff;
            if (r0 < NTOK) {
                float2 v = make_float2(acc[nt][0], acc[nt][1]);
                *reinterpret_cast<float2*>(&g_ao[((size_t)ww * NTOK + r0) * HID + h * DHEAD + d]) = v;
            }
            if (r0 + 8 < NTOK) {
                float2 v = make_float2(acc[nt][2], acc[nt][3]);
                *reinterpret_cast<float2*>(&g_ao[((size_t)ww * NTOK + r0 + 8) * HID + h * DHEAD + d]) = v;
            }
        }
    }
}

// ---------------- K3: output projection ----------------
__global__ void __launch_bounds__(128) fc_kernel(const float* __restrict__ fc_w,
                                                 const float* __restrict__ fc_b,
                                                 float* __restrict__ out) {
    __shared__ SmemGemm sm;
    float acc[2][12][4];
    #pragma unroll
    for (int a = 0; a < 2; a++)
        #pragma unroll
        for (int b = 0; b < 12; b++)
            #pragma unroll
            for (int c = 0; c < 4; c++) acc[a][b][c] = 0.f;

    const int n0 = blockIdx.x * 96;
    const int m0 = blockIdx.y * 128;
    run_gemm<true>(g_ao, fc_w, m0, n0, &sm, acc);

    const int lane = threadIdx.x & 31, wid = threadIdx.x >> 5;
    const int rr = lane >> 2, c2 = (lane & 3) << 1;
    #pragma unroll
    for (int mt = 0; mt < 2; mt++)
        #pragma unroll
        for (int nt = 0; nt < 12; nt++) {
            int row = m0 + wid * 32 + mt * 16 + rr;
            int col = n0 + nt * 8 + c2;
            float b0 = fc_b[col], b1 = fc_b[col + 1];
            float2 v0 = make_float2(acc[mt][nt][0] + b0, acc[mt][nt][1] + b1);
            float2 v1 = make_float2(acc[mt][nt][2] + b0, acc[mt][nt][3] + b1);
            *reinterpret_cast<float2*>(&out[(size_t)row * 384 + col])       = v0;
            *reinterpret_cast<float2*>(&out[(size_t)(row + 8) * 384 + col]) = v1;
        }
}

// ---------------- launch ----------------
extern "C" void kernel_launch(void* const* d_in, const int* in_sizes, int n_in,
                              void* d_out, int out_size) {
    const float* x    = (const float*)d_in[0];
    const float* tbl  = (const float*)d_in[1];
    const float* qw   = (const float*)d_in[2];
    const float* qb   = (const float*)d_in[3];
    const float* fw   = (const float*)d_in[4];
    const float* fb   = (const float*)d_in[5];
    const int*   ridx = (const int*)d_in[6];
    float* out = (float*)d_out;

    bias_kernel<<<(NHEAD * NTOK * NTOK + 255) / 256, 256>>>(tbl, ridx);
    qkv_kernel<<<dim3(NHEAD, MTOT / 128), 128>>>(x, qw, qb);
    attn_kernel<<<NWIN * NHEAD, 128>>>();
    fc_kernel<<<dim3(HID / 96, MTOT / 128), 128>>>(fw, fb, out);
}